// round 3
// baseline (speedup 1.0000x reference)
#include <cuda_runtime.h>
#include <math.h>

// ---------------------------------------------------------------------------
// AttentionLayer: B=16, T=4096, D=1024, NH=16, HD=64, Tq=1.
// Folded formulation (K/V never materialized):
//   qt[b,d,h] = SCALE * sum_j q[b,h*64+j] * Wk[h*64+j, d]
//   scores[b,h,t] = sum_d qt[b,d,h] * enc[b,t,d]          (pass A, streams enc)
//   attn = softmax_t(scores)
//   u[b,h,d] = sum_t attn[b,h,t] * enc[b,t,d]             (pass B, streams enc)
//   ctx[b,o] = Wv[o,:] . u[b, o>>6, :]
//   out = silu(cat(dec_h,ctx) @ W1^T) @ W2^T
// All dense layers are batched M=16 GEMMs (weights read once).
// ---------------------------------------------------------------------------

#define B_   16
#define T_   4096
#define D_   1024
#define NH_  16
#define HD_  64
#define NC_  32          // t-chunks for pass B partials
#define TCH_ 128         // rows per chunk (pass B)
#define TBLK_ 128        // t-rows per CTA (pass A)

typedef unsigned long long u64;

// scratch (no cudaMalloc allowed)
__device__ __align__(16) float g_q  [B_*D_];
__device__ __align__(16) float g_qt [B_*D_*NH_];        // [b][d][h] (scaled)
__device__ __align__(16) float g_sc [B_*NH_*T_];        // [b][h][t]
__device__ __align__(16) float g_at [B_*NH_*T_];        // [b][h][t]
__device__ __align__(16) float g_up [NC_*B_*NH_*D_];    // chunk partials of u
__device__ __align__(16) float g_u  [B_*NH_*D_];        // [b][h][d]
__device__ __align__(16) float g_ctx[B_*D_];
__device__ __align__(16) float g_hb [B_*4*D_];
__device__ __align__(16) float g_o4 [4*B_*D_];          // ffn2 K-split partials

// ---- packed f32x2 helpers -------------------------------------------------
__device__ __forceinline__ void fma2(u64 &acc, u64 a, u64 b) {
    asm("fma.rn.f32x2 %0, %1, %2, %0;" : "+l"(acc) : "l"(a), "l"(b));
}
__device__ __forceinline__ u64 pack2(float v) {
    u64 r; asm("mov.b64 %0, {%1, %1};" : "=l"(r) : "f"(v)); return r;
}
__device__ __forceinline__ u64 pack2b(float a, float b) {
    u64 r; asm("mov.b64 %0, {%1, %2};" : "=l"(r) : "f"(a), "f"(b)); return r;
}
__device__ __forceinline__ float2 unpack2(u64 v) {
    float2 r; asm("mov.b64 {%0, %1}, %2;" : "=f"(r.x), "=f"(r.y) : "l"(v)); return r;
}
__device__ __forceinline__ float wred(float s) {
    #pragma unroll
    for (int o = 16; o > 0; o >>= 1) s += __shfl_xor_sync(0xffffffffu, s, o);
    return s;
}

// ===========================================================================
// Batched M=16 GEMM building block: 256 threads, 32-row j tile, all 16 b.
// thread = (jj = tid>>3 in [0,32), bp = tid&7 owning b = {2bp, 2bp+1})
// Weights staged pre-packed (f32x2-replicated) in smem; X staged [k][b].
// Inner loop: LDS.64(W bcast) + LDS.64(X) + fma2  -> 3 issues / 4 FLOP.
// ===========================================================================

#define GEMM16_BODY(WLOAD, XLOAD, KLEN)                                       \
    int tid = threadIdx.x, jj = tid >> 3, bp = tid & 7;                        \
    __shared__ u64 Ws2[32 * 33];                                               \
    __shared__ __align__(16) float Xs[32 * 18];                                \
    u64 acc = 0ull;                                                            \
    for (int k0 = 0; k0 < (KLEN); k0 += 32) {                                  \
        _Pragma("unroll")                                                      \
        for (int i = 0; i < 4; i++) {                                          \
            int idx = i * 256 + tid; int r = idx >> 5, c = idx & 31;           \
            Ws2[r * 33 + c] = pack2(WLOAD(r, k0 + c));                         \
        }                                                                      \
        _Pragma("unroll")                                                      \
        for (int i = 0; i < 2; i++) {                                          \
            int idx = i * 256 + tid; int k = idx & 31, b = idx >> 5;           \
            Xs[k * 18 + b] = XLOAD(b, k0 + k);                                 \
        }                                                                      \
        __syncthreads();                                                       \
        _Pragma("unroll")                                                      \
        for (int k = 0; k < 32; k++)                                           \
            fma2(acc, Ws2[jj * 33 + k], *(const u64*)&Xs[k * 18 + bp * 2]);    \
        __syncthreads();                                                       \
    }                                                                          \
    float2 v = unpack2(acc);

// ---------------------------------------------------------------------------
// K1: q = dec_h @ Wq^T        grid 32, 256 thr
__global__ void k_qproj(const float* __restrict__ dec_h,
                        const float* __restrict__ Wq) {
    int j0 = blockIdx.x * 32;
#define WL(r, k) Wq[(size_t)(j0 + (r)) * D_ + (k)]
#define XL(b, k) dec_h[(size_t)(b) * D_ + (k)]
    GEMM16_BODY(WL, XL, D_)
#undef WL
#undef XL
    g_q[(size_t)(2 * bp)     * D_ + j0 + jj] = v.x;
    g_q[(size_t)(2 * bp + 1) * D_ + j0 + jj] = v.y;
}

// ---------------------------------------------------------------------------
// K2: qt[b][d][h] = SCALE * Wk_h^T q_h       grid 64 (h*4+quarter), 256 thr
__global__ void k_qtilde(const float* __restrict__ Wk) {
    int h = blockIdx.x >> 2, d0 = (blockIdx.x & 3) * 256, tid = threadIdx.x;
    __shared__ u64 qs2[64 * 8];          // [j][bpair]
    #pragma unroll
    for (int i = 0; i < 2; i++) {
        int idx = i * 256 + tid; int j = idx >> 3, bp = idx & 7;
        float a = g_q[(size_t)(2 * bp)     * D_ + h * HD_ + j];
        float b = g_q[(size_t)(2 * bp + 1) * D_ + h * HD_ + j];
        qs2[j * 8 + bp] = pack2b(a, b);
    }
    __syncthreads();
    u64 acc[8];
    #pragma unroll
    for (int bp = 0; bp < 8; bp++) acc[bp] = 0ull;
    #pragma unroll 4
    for (int j = 0; j < HD_; j++) {
        u64 w2 = pack2(Wk[(size_t)(h * HD_ + j) * D_ + d0 + tid]);
        #pragma unroll
        for (int bp = 0; bp < 8; bp++) fma2(acc[bp], w2, qs2[j * 8 + bp]);
    }
    #pragma unroll
    for (int bp = 0; bp < 8; bp++) {
        float2 v = unpack2(acc[bp]);
        g_qt[(size_t)(2 * bp)     * D_ * NH_ + (d0 + tid) * NH_ + h] = 0.125f * v.x;
        g_qt[(size_t)(2 * bp + 1) * D_ * NH_ + (d0 + tid) * NH_ + h] = 0.125f * v.y;
    }
}

// ---------------------------------------------------------------------------
// K3 (pass A): scores[b][h][t]   grid (16, 32), 128 thr (thread = 1 t-row)
__global__ void k_scores(const float* __restrict__ enc) {
    int b  = blockIdx.x;
    int t0 = blockIdx.y * TBLK_;
    int tid = threadIdx.x;
    __shared__ __align__(16) float enc_s[TBLK_ * 17];
    __shared__ __align__(16) float qt_s[16 * NH_];
    const float* encb = enc + ((size_t)b * T_ + t0) * D_;
    const float* qtb  = g_qt + (size_t)b * D_ * NH_;

    u64 acc[8];
    #pragma unroll
    for (int k = 0; k < 8; k++) acc[k] = 0ull;

    for (int dc = 0; dc < D_; dc += 16) {
        #pragma unroll
        for (int k = 0; k < 16; k++) {
            int idx = (k << 7) + tid;
            int r = idx >> 4, c = idx & 15;
            enc_s[r * 17 + c] = encb[(size_t)r * D_ + dc + c];
        }
        qt_s[tid]       = qtb[dc * NH_ + tid];
        qt_s[tid + 128] = qtb[dc * NH_ + tid + 128];
        __syncthreads();
        #pragma unroll
        for (int d = 0; d < 16; d++) {
            u64 e2 = pack2(enc_s[tid * 17 + d]);
            const ulonglong2* qp = (const ulonglong2*)(qt_s + (d << 4));
            ulonglong2 q0 = qp[0], q1 = qp[1], q2 = qp[2], q3 = qp[3];
            fma2(acc[0], e2, q0.x); fma2(acc[1], e2, q0.y);
            fma2(acc[2], e2, q1.x); fma2(acc[3], e2, q1.y);
            fma2(acc[4], e2, q2.x); fma2(acc[5], e2, q2.y);
            fma2(acc[6], e2, q3.x); fma2(acc[7], e2, q3.y);
        }
        __syncthreads();
    }
    int t = t0 + tid;
    #pragma unroll
    for (int k = 0; k < 8; k++) {
        float2 v = unpack2(acc[k]);
        g_sc[((size_t)b * NH_ + 2 * k    ) * T_ + t] = v.x;
        g_sc[((size_t)b * NH_ + 2 * k + 1) * T_ + t] = v.y;
    }
}

// ---------------------------------------------------------------------------
// K4: softmax over t per (b,h), [b][h][t] -> [b][h][t] (fully coalesced)
__global__ void k_softmax() {
    int bh = blockIdx.x, tid = threadIdx.x;          // 256 blocks x 256 thr
    const float4* sc4 = (const float4*)(g_sc + (size_t)bh * T_);
    float4*       at4 = (float4*)      (g_at + (size_t)bh * T_);
    __shared__ float red[8];
    __shared__ float sbc;

    float4 v[4];
    float m = -1e30f;
    #pragma unroll
    for (int k = 0; k < 4; k++) {
        v[k] = sc4[(k << 8) + tid];
        m = fmaxf(m, fmaxf(fmaxf(v[k].x, v[k].y), fmaxf(v[k].z, v[k].w)));
    }
    #pragma unroll
    for (int o = 16; o > 0; o >>= 1) m = fmaxf(m, __shfl_xor_sync(0xffffffffu, m, o));
    if ((tid & 31) == 0) red[tid >> 5] = m;
    __syncthreads();
    if (tid == 0) {
        float mm = red[0];
        #pragma unroll
        for (int i = 1; i < 8; i++) mm = fmaxf(mm, red[i]);
        sbc = mm;
    }
    __syncthreads();
    m = sbc;
    float s = 0.f;
    #pragma unroll
    for (int k = 0; k < 4; k++) {
        v[k].x = expf(v[k].x - m); v[k].y = expf(v[k].y - m);
        v[k].z = expf(v[k].z - m); v[k].w = expf(v[k].w - m);
        s += (v[k].x + v[k].y) + (v[k].z + v[k].w);
    }
    s = wred(s);
    __syncthreads();
    if ((tid & 31) == 0) red[tid >> 5] = s;
    __syncthreads();
    if (tid == 0) {
        float ss = 0.f;
        #pragma unroll
        for (int i = 0; i < 8; i++) ss += red[i];
        sbc = 1.f / ss;
    }
    __syncthreads();
    float inv = sbc;
    #pragma unroll
    for (int k = 0; k < 4; k++) {
        v[k].x *= inv; v[k].y *= inv; v[k].z *= inv; v[k].w *= inv;
        at4[(k << 8) + tid] = v[k];
    }
}

// ---------------------------------------------------------------------------
// K5 (pass B): u_part[c][b][h][d] over 128-row chunks   grid (16,32), 256 thr
__global__ void k_wsum(const float* __restrict__ enc) {
    int b = blockIdx.x, c = blockIdx.y;
    int tid = threadIdx.x;
    __shared__ __align__(16) float w_s[TCH_ * NH_];
    #pragma unroll
    for (int i = 0; i < 8; i++) {
        int idx = (i << 8) + tid;
        int h = idx >> 7, t = idx & 127;
        w_s[t * NH_ + h] = g_at[((size_t)b * NH_ + h) * T_ + c * TCH_ + t];
    }
    __syncthreads();

    u64 u[4][8];
    #pragma unroll
    for (int d = 0; d < 4; d++)
        #pragma unroll
        for (int hp = 0; hp < 8; hp++) u[d][hp] = 0ull;

    const float4* e4 = (const float4*)(enc + ((size_t)b * T_ + (size_t)c * TCH_) * D_) + tid;
    #pragma unroll 4
    for (int t = 0; t < TCH_; t++) {
        float4 ev = e4[(size_t)t * (D_ / 4)];
        const ulonglong2* wp = (const ulonglong2*)(w_s + t * NH_);
        ulonglong2 w0 = wp[0], w1 = wp[1], w2 = wp[2], w3 = wp[3];
        u64 e0 = pack2(ev.x), e1 = pack2(ev.y), e2 = pack2(ev.z), e3 = pack2(ev.w);
        fma2(u[0][0], e0, w0.x); fma2(u[0][1], e0, w0.y);
        fma2(u[0][2], e0, w1.x); fma2(u[0][3], e0, w1.y);
        fma2(u[0][4], e0, w2.x); fma2(u[0][5], e0, w2.y);
        fma2(u[0][6], e0, w3.x); fma2(u[0][7], e0, w3.y);
        fma2(u[1][0], e1, w0.x); fma2(u[1][1], e1, w0.y);
        fma2(u[1][2], e1, w1.x); fma2(u[1][3], e1, w1.y);
        fma2(u[1][4], e1, w2.x); fma2(u[1][5], e1, w2.y);
        fma2(u[1][6], e1, w3.x); fma2(u[1][7], e1, w3.y);
        fma2(u[2][0], e2, w0.x); fma2(u[2][1], e2, w0.y);
        fma2(u[2][2], e2, w1.x); fma2(u[2][3], e2, w1.y);
        fma2(u[2][4], e2, w2.x); fma2(u[2][5], e2, w2.y);
        fma2(u[2][6], e2, w3.x); fma2(u[2][7], e2, w3.y);
        fma2(u[3][0], e3, w0.x); fma2(u[3][1], e3, w0.y);
        fma2(u[3][2], e3, w1.x); fma2(u[3][3], e3, w1.y);
        fma2(u[3][4], e3, w2.x); fma2(u[3][5], e3, w2.y);
        fma2(u[3][6], e3, w3.x); fma2(u[3][7], e3, w3.y);
    }
    #pragma unroll
    for (int hp = 0; hp < 8; hp++) {
        float2 a0 = unpack2(u[0][hp]), a1 = unpack2(u[1][hp]),
               a2 = unpack2(u[2][hp]), a3 = unpack2(u[3][hp]);
        float4 lo = make_float4(a0.x, a1.x, a2.x, a3.x);
        float4 hi = make_float4(a0.y, a1.y, a2.y, a3.y);
        size_t base = (((size_t)c * B_ + b) * NH_) * D_ + 4 * tid;
        *(float4*)(g_up + base + (size_t)(2 * hp)     * D_) = lo;
        *(float4*)(g_up + base + (size_t)(2 * hp + 1) * D_) = hi;
    }
}

// ---------------------------------------------------------------------------
// K6: u = sum_c u_part
__global__ void k_combine() {
    int idx = blockIdx.x * 256 + threadIdx.x;   // B*NH*D = 262144
    float s = 0.f;
    #pragma unroll
    for (int c = 0; c < NC_; c++) s += g_up[(size_t)c * (B_ * NH_ * D_) + idx];
    g_u[idx] = s;
}

// ---------------------------------------------------------------------------
// K7: ctx[b,o] = Wv[o,:] . u[b, o>>6, :]     grid 32, 256 thr
__global__ void k_ctx(const float* __restrict__ Wv) {
    int j0 = blockIdx.x * 32;
    int h  = j0 >> 6;
#define WL(r, k) Wv[(size_t)(j0 + (r)) * D_ + (k)]
#define XL(b, k) g_u[((size_t)(b) * NH_ + h) * D_ + (k)]
    GEMM16_BODY(WL, XL, D_)
#undef WL
#undef XL
    g_ctx[(size_t)(2 * bp)     * D_ + j0 + jj] = v.x;
    g_ctx[(size_t)(2 * bp + 1) * D_ + j0 + jj] = v.y;
}

// ---------------------------------------------------------------------------
// K8: h = silu(cat(dec_h, ctx) @ W1^T)       grid 128, 256 thr
__global__ void k_ffn1(const float* __restrict__ dec_h,
                       const float* __restrict__ W1) {
    int j0 = blockIdx.x * 32;
#define WL(r, k) W1[(size_t)(j0 + (r)) * (2 * D_) + (k)]
#define XL(b, k) ((k) < D_ ? dec_h[(size_t)(b) * D_ + (k)] \
                           : g_ctx[(size_t)(b) * D_ + (k) - D_])
    GEMM16_BODY(WL, XL, 2 * D_)
#undef WL
#undef XL
    g_hb[(size_t)(2 * bp)     * (4 * D_) + j0 + jj] = v.x / (1.f + expf(-v.x));
    g_hb[(size_t)(2 * bp + 1) * (4 * D_) + j0 + jj] = v.y / (1.f + expf(-v.y));
}

// ---------------------------------------------------------------------------
// K9: out partials = h @ W2^T (K split 4)    grid (32,4), 256 thr
__global__ void k_ffn2(const float* __restrict__ W2) {
    int j0 = blockIdx.x * 32;
    int kb = blockIdx.y * 1024;
#define WL(r, k) W2[(size_t)(j0 + (r)) * (4 * D_) + kb + (k)]
#define XL(b, k) g_hb[(size_t)(b) * (4 * D_) + kb + (k)]
    GEMM16_BODY(WL, XL, 1024)
#undef WL
#undef XL
    g_o4[(size_t)blockIdx.y * (B_ * D_) + (2 * bp)     * D_ + j0 + jj] = v.x;
    g_o4[(size_t)blockIdx.y * (B_ * D_) + (2 * bp + 1) * D_ + j0 + jj] = v.y;
}

// ---------------------------------------------------------------------------
// K10: final reduce of ffn2 K-split partials
__global__ void k_fin(float* __restrict__ outp) {
    int i = blockIdx.x * 256 + threadIdx.x;     // 16384
    outp[i] = ((g_o4[i] + g_o4[i + B_ * D_]) +
               (g_o4[i + 2 * B_ * D_] + g_o4[i + 3 * B_ * D_]));
}

// ---------------------------------------------------------------------------
extern "C" void kernel_launch(void* const* d_in, const int* in_sizes, int n_in,
                              void* d_out, int out_size) {
    const float* dec_h = (const float*)d_in[0];
    const float* enc   = (const float*)d_in[1];
    const float* Wq    = (const float*)d_in[2];
    const float* Wk    = (const float*)d_in[3];
    const float* Wv    = (const float*)d_in[4];
    const float* W1    = (const float*)d_in[5];
    const float* W2    = (const float*)d_in[6];
    float* outp = (float*)d_out;

    k_qproj  <<<32, 256>>>(dec_h, Wq);
    k_qtilde <<<64, 256>>>(Wk);
    k_scores <<<dim3(B_, T_ / TBLK_), 128>>>(enc);
    k_softmax<<<B_ * NH_, 256>>>();
    k_wsum   <<<dim3(B_, NC_), 256>>>(enc);
    k_combine<<<(B_ * NH_ * D_) / 256, 256>>>();
    k_ctx    <<<32, 256>>>(Wv);
    k_ffn1   <<<128, 256>>>(dec_h, W1);
    k_ffn2   <<<dim3(32, 4), 256>>>(W2);
    k_fin    <<<64, 256>>>(outp);
}

// round 5
// speedup vs baseline: 1.4192x; 1.4192x over previous
#include <cuda_runtime.h>
#include <math.h>

// ---------------------------------------------------------------------------
// AttentionLayer: B=16, T=4096, D=1024, NH=16, HD=64, Tq=1.
// Folded formulation (K/V never materialized):
//   qt[b,d,h]   = SCALE * sum_j q[b,h*64+j] * Wk[h*64+j, d]
//   scores      = enc . qt            (pass A, streams enc once)
//   attn        = softmax_t(scores)
//   u[b,h,d]    = sum_t attn * enc    (pass B, streams enc once)
//   ctx         = Wv . u  ;  out = silu(cat(dec_h,ctx) @ W1^T) @ W2^T
// Dense layers: 64-j-tile batched M=16 GEMMs, double-buffered smem staging.
// ---------------------------------------------------------------------------

#define B_   16
#define T_   4096
#define D_   1024
#define NH_  16
#define HD_  64
#define NC_  32
#define TCH_ 128

typedef unsigned long long u64;

// scratch (no cudaMalloc allowed)
__device__ __align__(16) float g_qp [4*B_*D_];          // qproj K-split partials
__device__ __align__(16) float g_qt [B_*D_*NH_];        // [b][d][h] (scaled)
__device__ __align__(16) float g_sc [B_*NH_*T_];
__device__ __align__(16) float g_at [B_*NH_*T_];
__device__ __align__(16) float g_up [NC_*B_*NH_*D_];
__device__ __align__(16) float g_u  [B_*NH_*D_];
__device__ __align__(16) float g_cp [2*B_*D_];          // ctx K-split partials
__device__ __align__(16) float g_h4 [2*B_*4*D_];        // ffn1 K-split partials
__device__ __align__(16) float g_hb [B_*4*D_];
__device__ __align__(16) float g_o8 [8*B_*D_];          // ffn2 K-split partials

// ---- packed f32x2 helpers -------------------------------------------------
__device__ __forceinline__ void fma2(u64 &acc, u64 a, u64 b) {
    asm("fma.rn.f32x2 %0, %1, %2, %0;" : "+l"(acc) : "l"(a), "l"(b));
}
__device__ __forceinline__ u64 pack2(float v) {
    u64 r; asm("mov.b64 %0, {%1, %1};" : "=l"(r) : "f"(v)); return r;
}
__device__ __forceinline__ u64 pack2b(float a, float b) {
    u64 r; asm("mov.b64 %0, {%1, %2};" : "=l"(r) : "f"(a), "f"(b)); return r;
}
__device__ __forceinline__ float2 unpack2(u64 v) {
    float2 r; asm("mov.b64 {%0, %1}, %2;" : "=f"(r.x), "=f"(r.y) : "l"(v)); return r;
}
__device__ __forceinline__ float wred(float s) {
    #pragma unroll
    for (int o = 16; o > 0; o >>= 1) s += __shfl_xor_sync(0xffffffffu, s, o);
    return s;
}

// ===========================================================================
// GEMM64: 256 threads compute a 64-j tile x all 16 b over NCHUNK*32 k-values.
// thread: jj = tid>>3 owns rows j0+jj and j0+32+jj; bp = tid&7 owns b pair.
// Double-buffered smem; weights pre-packed (f32x2-replicated) u64.
// Per k: 2x LDS.64 (W, 4-addr bcast) + LDS.64 (X) + 2 indep fma2 chains.
// ===========================================================================
#define GEMM64(WL4, XL, NCHUNK, KOFF)                                          \
    int tid = threadIdx.x, jj = tid >> 3, bp = tid & 7;                        \
    __shared__ u64  Ws[2][64][34];                                             \
    __shared__ float Xs[2][32][18];                                            \
    u64 accA = 0ull, accB = 0ull;                                              \
    const int r0 = tid >> 3, c0 = (tid * 4) & 31;                              \
    const int r1 = 32 + r0,  c1 = c0;                                          \
    const int xk = tid & 31, xb = tid >> 5;                                    \
    float4 w0, w1; float x0, x1;                                               \
    w0 = WL4(r0, (KOFF) + c0); w1 = WL4(r1, (KOFF) + c1);                      \
    x0 = XL(xb, (KOFF) + xk);  x1 = XL(xb + 8, (KOFF) + xk);                   \
    {                                                                          \
        ulonglong2* p0 = (ulonglong2*)&Ws[0][r0][c0];                          \
        p0[0] = make_ulonglong2(pack2(w0.x), pack2(w0.y));                     \
        p0[1] = make_ulonglong2(pack2(w0.z), pack2(w0.w));                     \
        ulonglong2* p1 = (ulonglong2*)&Ws[0][r1][c1];                          \
        p1[0] = make_ulonglong2(pack2(w1.x), pack2(w1.y));                     \
        p1[1] = make_ulonglong2(pack2(w1.z), pack2(w1.w));                     \
        Xs[0][xk][xb] = x0; Xs[0][xk][xb + 8] = x1;                            \
    }                                                                          \
    __syncthreads();                                                           \
    for (int ch = 0; ch < (NCHUNK); ch++) {                                    \
        int cur = ch & 1;                                                      \
        if (ch + 1 < (NCHUNK)) {                                               \
            int kb = (KOFF) + (ch + 1) * 32;                                   \
            w0 = WL4(r0, kb + c0); w1 = WL4(r1, kb + c1);                      \
            x0 = XL(xb, kb + xk);  x1 = XL(xb + 8, kb + xk);                   \
        }                                                                      \
        _Pragma("unroll")                                                      \
        for (int k = 0; k < 32; k++) {                                         \
            u64 xv = *(const u64*)&Xs[cur][k][bp * 2];                         \
            fma2(accA, Ws[cur][jj][k],      xv);                               \
            fma2(accB, Ws[cur][32 + jj][k], xv);                               \
        }                                                                      \
        if (ch + 1 < (NCHUNK)) {                                               \
            int nxt = cur ^ 1;                                                 \
            ulonglong2* p0 = (ulonglong2*)&Ws[nxt][r0][c0];                    \
            p0[0] = make_ulonglong2(pack2(w0.x), pack2(w0.y));                 \
            p0[1] = make_ulonglong2(pack2(w0.z), pack2(w0.w));                 \
            ulonglong2* p1 = (ulonglong2*)&Ws[nxt][r1][c1];                    \
            p1[0] = make_ulonglong2(pack2(w1.x), pack2(w1.y));                 \
            p1[1] = make_ulonglong2(pack2(w1.z), pack2(w1.w));                 \
            Xs[nxt][xk][xb] = x0; Xs[nxt][xk][xb + 8] = x1;                    \
        }                                                                      \
        __syncthreads();                                                       \
    }                                                                          \
    float2 vA = unpack2(accA), vB = unpack2(accB);

// ---------------------------------------------------------------------------
// K1: qproj partials.  grid (16 jb, 4 ks), 256 thr
__global__ __launch_bounds__(256) void k_qproj(const float* __restrict__ dec_h,
                                               const float* __restrict__ Wq) {
    int j0 = blockIdx.x * 64, ks = blockIdx.y;
#define WL4(r, k) (*(const float4*)&Wq[(size_t)(j0 + (r)) * D_ + (k)])
#define XLD(b, k) dec_h[(size_t)(b) * D_ + (k)]
    GEMM64(WL4, XLD, 8, ks * 256)
#undef WL4
#undef XLD
    float* o = g_qp + (size_t)ks * (B_ * D_);
    o[(size_t)(2 * bp)     * D_ + j0 + jj]      = vA.x;
    o[(size_t)(2 * bp + 1) * D_ + j0 + jj]      = vA.y;
    o[(size_t)(2 * bp)     * D_ + j0 + 32 + jj] = vB.x;
    o[(size_t)(2 * bp + 1) * D_ + j0 + 32 + jj] = vB.y;
}

// ---------------------------------------------------------------------------
// K2: qt[b][d][h] = SCALE * Wk_h^T q_h (sums the 4 qproj partials)
// grid 64 (h*4+quarter), 256 thr
__global__ __launch_bounds__(256) void k_qtilde(const float* __restrict__ Wk) {
    int h = blockIdx.x >> 2, d0 = (blockIdx.x & 3) * 256, tid = threadIdx.x;
    __shared__ u64 qs2[64 * 8];          // [j][bpair]
    #pragma unroll
    for (int i = 0; i < 2; i++) {
        int idx = i * 256 + tid; int j = idx >> 3, bpp = idx & 7;
        float a = 0.f, bb = 0.f;
        #pragma unroll
        for (int ks = 0; ks < 4; ks++) {
            a  += g_qp[(size_t)ks * (B_ * D_) + (2 * bpp)     * D_ + h * HD_ + j];
            bb += g_qp[(size_t)ks * (B_ * D_) + (2 * bpp + 1) * D_ + h * HD_ + j];
        }
        qs2[j * 8 + bpp] = pack2b(a, bb);
    }
    __syncthreads();
    u64 acc[8];
    #pragma unroll
    for (int bp = 0; bp < 8; bp++) acc[bp] = 0ull;
    #pragma unroll 4
    for (int j = 0; j < HD_; j++) {
        u64 w2 = pack2(Wk[(size_t)(h * HD_ + j) * D_ + d0 + tid]);
        #pragma unroll
        for (int bp = 0; bp < 8; bp++) fma2(acc[bp], w2, qs2[j * 8 + bp]);
    }
    #pragma unroll
    for (int bp = 0; bp < 8; bp++) {
        float2 v = unpack2(acc[bp]);
        g_qt[(size_t)(2 * bp)     * D_ * NH_ + (d0 + tid) * NH_ + h] = 0.125f * v.x;
        g_qt[(size_t)(2 * bp + 1) * D_ * NH_ + (d0 + tid) * NH_ + h] = 0.125f * v.y;
    }
}

// ---------------------------------------------------------------------------
// K3 (pass A): scores[b][h][t]   grid (16, 32), 256 thr
// thread = (row = tid>>1 of 128 t-rows, hh = tid&1 owning 8 heads)
// double-buffered 16-d chunks.
__global__ __launch_bounds__(256) void k_scores(const float* __restrict__ enc) {
    int b = blockIdx.x, t0 = blockIdx.y * 128, tid = threadIdx.x;
    int row = tid >> 1, hh = tid & 1;
    __shared__ float es[2][128][18];
    __shared__ float qs[2][16][16];
    const float* encb = enc + ((size_t)b * T_ + t0) * D_;
    const float* qtb  = g_qt + (size_t)b * D_ * NH_;
    const int r0 = tid >> 2, c0 = (tid * 4) & 15;
    const int r1 = 64 + r0,  c1 = c0;
    const int qd = tid >> 4, qh = tid & 15;

    u64 acc0 = 0ull, acc1 = 0ull, acc2 = 0ull, acc3 = 0ull;
    float4 e0, e1; float qv;
    e0 = *(const float4*)&encb[(size_t)r0 * D_ + c0];
    e1 = *(const float4*)&encb[(size_t)r1 * D_ + c1];
    qv = qtb[qd * NH_ + qh];
    *(u64*)&es[0][r0][c0]     = pack2b(e0.x, e0.y);
    *(u64*)&es[0][r0][c0 + 2] = pack2b(e0.z, e0.w);
    *(u64*)&es[0][r1][c1]     = pack2b(e1.x, e1.y);
    *(u64*)&es[0][r1][c1 + 2] = pack2b(e1.z, e1.w);
    qs[0][qd][qh] = qv;
    __syncthreads();

    for (int ch = 0; ch < 64; ch++) {
        int cur = ch & 1;
        if (ch + 1 < 64) {
            int dc = (ch + 1) * 16;
            e0 = *(const float4*)&encb[(size_t)r0 * D_ + dc + c0];
            e1 = *(const float4*)&encb[(size_t)r1 * D_ + dc + c1];
            qv = qtb[(dc + qd) * NH_ + qh];
        }
        #pragma unroll
        for (int d = 0; d < 16; d++) {
            u64 e2 = pack2(es[cur][row][d]);
            const u64* qp = (const u64*)&qs[cur][d][hh * 8];
            fma2(acc0, e2, qp[0]); fma2(acc1, e2, qp[1]);
            fma2(acc2, e2, qp[2]); fma2(acc3, e2, qp[3]);
        }
        if (ch + 1 < 64) {
            int nxt = cur ^ 1;
            *(u64*)&es[nxt][r0][c0]     = pack2b(e0.x, e0.y);
            *(u64*)&es[nxt][r0][c0 + 2] = pack2b(e0.z, e0.w);
            *(u64*)&es[nxt][r1][c1]     = pack2b(e1.x, e1.y);
            *(u64*)&es[nxt][r1][c1 + 2] = pack2b(e1.z, e1.w);
            qs[nxt][qd][qh] = qv;
        }
        __syncthreads();
    }
    int t = t0 + row;
    float2 v;
    int hbase = hh * 8;
    v = unpack2(acc0);
    g_sc[((size_t)b * NH_ + hbase + 0) * T_ + t] = v.x;
    g_sc[((size_t)b * NH_ + hbase + 1) * T_ + t] = v.y;
    v = unpack2(acc1);
    g_sc[((size_t)b * NH_ + hbase + 2) * T_ + t] = v.x;
    g_sc[((size_t)b * NH_ + hbase + 3) * T_ + t] = v.y;
    v = unpack2(acc2);
    g_sc[((size_t)b * NH_ + hbase + 4) * T_ + t] = v.x;
    g_sc[((size_t)b * NH_ + hbase + 5) * T_ + t] = v.y;
    v = unpack2(acc3);
    g_sc[((size_t)b * NH_ + hbase + 6) * T_ + t] = v.x;
    g_sc[((size_t)b * NH_ + hbase + 7) * T_ + t] = v.y;
}

// ---------------------------------------------------------------------------
// K4: softmax over t per (b,h), [b][h][t], fully coalesced float4
__global__ __launch_bounds__(256) void k_softmax() {
    int bh = blockIdx.x, tid = threadIdx.x;
    const float4* sc4 = (const float4*)(g_sc + (size_t)bh * T_);
    float4*       at4 = (float4*)      (g_at + (size_t)bh * T_);
    __shared__ float red[8];
    __shared__ float sbc;

    float4 v[4];
    float m = -1e30f;
    #pragma unroll
    for (int k = 0; k < 4; k++) {
        v[k] = sc4[(k << 8) + tid];
        m = fmaxf(m, fmaxf(fmaxf(v[k].x, v[k].y), fmaxf(v[k].z, v[k].w)));
    }
    #pragma unroll
    for (int o = 16; o > 0; o >>= 1) m = fmaxf(m, __shfl_xor_sync(0xffffffffu, m, o));
    if ((tid & 31) == 0) red[tid >> 5] = m;
    __syncthreads();
    if (tid == 0) {
        float mm = red[0];
        #pragma unroll
        for (int i = 1; i < 8; i++) mm = fmaxf(mm, red[i]);
        sbc = mm;
    }
    __syncthreads();
    m = sbc;
    float s = 0.f;
    #pragma unroll
    for (int k = 0; k < 4; k++) {
        v[k].x = expf(v[k].x - m); v[k].y = expf(v[k].y - m);
        v[k].z = expf(v[k].z - m); v[k].w = expf(v[k].w - m);
        s += (v[k].x + v[k].y) + (v[k].z + v[k].w);
    }
    s = wred(s);
    __syncthreads();
    if ((tid & 31) == 0) red[tid >> 5] = s;
    __syncthreads();
    if (tid == 0) {
        float ss = 0.f;
        #pragma unroll
        for (int i = 0; i < 8; i++) ss += red[i];
        sbc = 1.f / ss;
    }
    __syncthreads();
    float inv = sbc;
    #pragma unroll
    for (int k = 0; k < 4; k++) {
        v[k].x *= inv; v[k].y *= inv; v[k].z *= inv; v[k].w *= inv;
        at4[(k << 8) + tid] = v[k];
    }
}

// ---------------------------------------------------------------------------
// K5 (pass B): u_part[c][b][h][d], 128-row chunks   grid (16,32), 256 thr
__global__ __launch_bounds__(256) void k_wsum(const float* __restrict__ enc) {
    int b = blockIdx.x, c = blockIdx.y, tid = threadIdx.x;
    __shared__ float w_s[TCH_][18];                 // pad 18: conflict-light
    #pragma unroll
    for (int i = 0; i < 8; i++) {
        int idx = (i << 8) + tid;
        int h = idx >> 7, t = idx & 127;
        w_s[t][h] = g_at[((size_t)b * NH_ + h) * T_ + c * TCH_ + t];
    }
    __syncthreads();

    u64 u[4][8];
    #pragma unroll
    for (int d = 0; d < 4; d++)
        #pragma unroll
        for (int hp = 0; hp < 8; hp++) u[d][hp] = 0ull;

    const float4* e4 = (const float4*)(enc + ((size_t)b * T_ + (size_t)c * TCH_) * D_) + tid;
    #pragma unroll 8
    for (int t = 0; t < TCH_; t++) {
        float4 ev = e4[(size_t)t * (D_ / 4)];
        const u64* wp = (const u64*)&w_s[t][0];     // 8x LDS.64 broadcast
        u64 e0 = pack2(ev.x), e1 = pack2(ev.y), e2 = pack2(ev.z), e3 = pack2(ev.w);
        #pragma unroll
        for (int hp = 0; hp < 8; hp++) {
            u64 w2 = wp[hp];
            fma2(u[0][hp], e0, w2);
            fma2(u[1][hp], e1, w2);
            fma2(u[2][hp], e2, w2);
            fma2(u[3][hp], e3, w2);
        }
    }
    #pragma unroll
    for (int hp = 0; hp < 8; hp++) {
        float2 a0 = unpack2(u[0][hp]), a1 = unpack2(u[1][hp]),
               a2 = unpack2(u[2][hp]), a3 = unpack2(u[3][hp]);
        float4 lo = make_float4(a0.x, a1.x, a2.x, a3.x);
        float4 hi = make_float4(a0.y, a1.y, a2.y, a3.y);
        size_t base = (((size_t)c * B_ + b) * NH_) * D_ + 4 * tid;
        *(float4*)(g_up + base + (size_t)(2 * hp)     * D_) = lo;
        *(float4*)(g_up + base + (size_t)(2 * hp + 1) * D_) = hi;
    }
}

// ---------------------------------------------------------------------------
// K6: u = sum_c u_part
__global__ __launch_bounds__(256) void k_combine() {
    int idx = blockIdx.x * 256 + threadIdx.x;
    float s = 0.f;
    #pragma unroll
    for (int c = 0; c < NC_; c++) s += g_up[(size_t)c * (B_ * NH_ * D_) + idx];
    g_u[idx] = s;
}

// ---------------------------------------------------------------------------
// K7: ctx partials = Wv . u     grid (16 jb, 2 ks)
__global__ __launch_bounds__(256) void k_ctx(const float* __restrict__ Wv) {
    int j0 = blockIdx.x * 64, ks = blockIdx.y;
    int h  = blockIdx.x;                 // j0>>6
#define WL4(r, k) (*(const float4*)&Wv[(size_t)(j0 + (r)) * D_ + (k)])
#define XLD(b, k) g_u[((size_t)(b) * NH_ + h) * D_ + (k)]
    GEMM64(WL4, XLD, 16, ks * 512)
#undef WL4
#undef XLD
    float* o = g_cp + (size_t)ks * (B_ * D_);
    o[(size_t)(2 * bp)     * D_ + j0 + jj]      = vA.x;
    o[(size_t)(2 * bp + 1) * D_ + j0 + jj]      = vA.y;
    o[(size_t)(2 * bp)     * D_ + j0 + 32 + jj] = vB.x;
    o[(size_t)(2 * bp + 1) * D_ + j0 + 32 + jj] = vB.y;
}

// ---------------------------------------------------------------------------
// K8: ffn1 partials = cat(dec_h, ctx) @ W1^T   grid (64 jb, 2 ks)
__global__ __launch_bounds__(256) void k_ffn1(const float* __restrict__ dec_h,
                                              const float* __restrict__ W1) {
    int j0 = blockIdx.x * 64, ks = blockIdx.y;
#define WL4(r, k) (*(const float4*)&W1[(size_t)(j0 + (r)) * (2 * D_) + (k)])
#define XLD(b, k) ((k) < D_ ? dec_h[(size_t)(b) * D_ + (k)]                    \
                            : (g_cp[(size_t)(b) * D_ + (k) - D_] +             \
                               g_cp[(size_t)(B_ * D_) + (b) * D_ + (k) - D_]))
    GEMM64(WL4, XLD, 32, ks * 1024)
#undef WL4
#undef XLD
    float* o = g_h4 + (size_t)ks * (B_ * 4 * D_);
    o[(size_t)(2 * bp)     * (4 * D_) + j0 + jj]      = vA.x;
    o[(size_t)(2 * bp + 1) * (4 * D_) + j0 + jj]      = vA.y;
    o[(size_t)(2 * bp)     * (4 * D_) + j0 + 32 + jj] = vB.x;
    o[(size_t)(2 * bp + 1) * (4 * D_) + j0 + 32 + jj] = vB.y;
}

// ---------------------------------------------------------------------------
// K9: hb = silu(h4[0] + h4[1])     grid 64, 256 thr, float4
__global__ __launch_bounds__(256) void k_silu() {
    int i = (blockIdx.x * 256 + threadIdx.x) * 4;
    float4 a = *(const float4*)&g_h4[i];
    float4 b = *(const float4*)&g_h4[(size_t)(B_ * 4 * D_) + i];
    float4 r;
    float s;
    s = a.x + b.x; r.x = s / (1.f + expf(-s));
    s = a.y + b.y; r.y = s / (1.f + expf(-s));
    s = a.z + b.z; r.z = s / (1.f + expf(-s));
    s = a.w + b.w; r.w = s / (1.f + expf(-s));
    *(float4*)&g_hb[i] = r;
}

// ---------------------------------------------------------------------------
// K10: ffn2 partials = hb @ W2^T   grid (16 jb, 8 ks)
__global__ __launch_bounds__(256) void k_ffn2(const float* __restrict__ W2) {
    int j0 = blockIdx.x * 64, ks = blockIdx.y;
#define WL4(r, k) (*(const float4*)&W2[(size_t)(j0 + (r)) * (4 * D_) + (k)])
#define XLD(b, k) g_hb[(size_t)(b) * (4 * D_) + (k)]
    GEMM64(WL4, XLD, 16, ks * 512)
#undef WL4
#undef XLD
    float* o = g_o8 + (size_t)ks * (B_ * D_);
    o[(size_t)(2 * bp)     * D_ + j0 + jj]      = vA.x;
    o[(size_t)(2 * bp + 1) * D_ + j0 + jj]      = vA.y;
    o[(size_t)(2 * bp)     * D_ + j0 + 32 + jj] = vB.x;
    o[(size_t)(2 * bp + 1) * D_ + j0 + 32 + jj] = vB.y;
}

// ---------------------------------------------------------------------------
// K11: out = sum of 8 ffn2 partials   grid 16, 256 thr, float4
__global__ __launch_bounds__(256) void k_fin(float* __restrict__ outp) {
    int i = (blockIdx.x * 256 + threadIdx.x) * 4;
    float4 s = *(const float4*)&g_o8[i];
    #pragma unroll
    for (int ks = 1; ks < 8; ks++) {
        float4 p = *(const float4*)&g_o8[(size_t)ks * (B_ * D_) + i];
        s.x += p.x; s.y += p.y; s.z += p.z; s.w += p.w;
    }
    *(float4*)&outp[i] = s;
}

// ---------------------------------------------------------------------------
extern "C" void kernel_launch(void* const* d_in, const int* in_sizes, int n_in,
                              void* d_out, int out_size) {
    const float* dec_h = (const float*)d_in[0];
    const float* enc   = (const float*)d_in[1];
    const float* Wq    = (const float*)d_in[2];
    const float* Wk    = (const float*)d_in[3];
    const float* Wv    = (const float*)d_in[4];
    const float* W1    = (const float*)d_in[5];
    const float* W2    = (const float*)d_in[6];
    float* outp = (float*)d_out;

    k_qproj  <<<dim3(16, 4), 256>>>(dec_h, Wq);
    k_qtilde <<<64, 256>>>(Wk);
    k_scores <<<dim3(16, 32), 256>>>(enc);
    k_softmax<<<256, 256>>>();
    k_wsum   <<<dim3(16, 32), 256>>>(enc);
    k_combine<<<1024, 256>>>();
    k_ctx    <<<dim3(16, 2), 256>>>(Wv);
    k_ffn1   <<<dim3(64, 2), 256>>>(dec_h, W1);
    k_silu   <<<64, 256>>>();
    k_ffn2   <<<dim3(16, 8), 256>>>(W2);
    k_fin    <<<16, 256>>>(outp);
}

// round 6
// speedup vs baseline: 1.6941x; 1.1937x over previous
#include <cuda_runtime.h>
#include <math.h>

// ---------------------------------------------------------------------------
// AttentionLayer: B=16, T=4096, D=1024, NH=16, HD=64, Tq=1.
// Folded formulation (K/V never materialized):
//   qt[b,d,h]   = SCALE * sum_j q[b,h*64+j] * Wk[h*64+j, d]
//   scores      = enc . qt            (pass A, streams enc once)
//   attn        = softmax_t(scores)
//   u[b,h,d]    = sum_t attn * enc    (pass B, streams enc once)
//   ctx         = Wv . u  ;  out = silu(cat(dec_h,ctx) @ W1^T) @ W2^T
// ---------------------------------------------------------------------------

#define B_   16
#define T_   4096
#define D_   1024
#define NH_  16
#define HD_  64
#define NC_  32
#define TCH_ 128

typedef unsigned long long u64;

// scratch (no cudaMalloc allowed)
__device__ __align__(16) float g_qp [8*B_*D_];          // qproj K-split partials
__device__ __align__(16) float g_qt [B_*D_*NH_];        // [b][d][h] (scaled)
__device__ __align__(16) float g_sc [B_*NH_*T_];
__device__ __align__(16) float g_at [B_*NH_*T_];
__device__ __align__(16) float g_up [NC_*B_*NH_*D_];
__device__ __align__(16) float g_u  [B_*NH_*D_];
__device__ __align__(16) float g_cp [8*B_*D_];          // ctx K-split partials
__device__ __align__(16) float g_ctx[B_*D_];
__device__ __align__(16) float g_h4 [4*B_*4*D_];        // ffn1 K-split partials
__device__ __align__(16) float g_hb [B_*4*D_];
__device__ __align__(16) float g_o8 [8*B_*D_];          // ffn2 K-split partials

// ---- packed f32x2 helpers -------------------------------------------------
__device__ __forceinline__ void fma2(u64 &acc, u64 a, u64 b) {
    asm("fma.rn.f32x2 %0, %1, %2, %0;" : "+l"(acc) : "l"(a), "l"(b));
}
__device__ __forceinline__ u64 pack2(float v) {
    u64 r; asm("mov.b64 %0, {%1, %1};" : "=l"(r) : "f"(v)); return r;
}
__device__ __forceinline__ u64 pack2b(float a, float b) {
    u64 r; asm("mov.b64 %0, {%1, %2};" : "=l"(r) : "f"(a), "f"(b)); return r;
}
__device__ __forceinline__ float2 unpack2(u64 v) {
    float2 r; asm("mov.b64 {%0, %1}, %2;" : "=f"(r.x), "=f"(r.y) : "l"(v)); return r;
}
__device__ __forceinline__ float wred(float s) {
    #pragma unroll
    for (int o = 16; o > 0; o >>= 1) s += __shfl_xor_sync(0xffffffffu, s, o);
    return s;
}

// ===========================================================================
// GEMM64: 256 threads compute a 64-j tile x all 16 b over NCHUNK*32 k-values.
// Double-buffered smem; weights pre-packed (f32x2-replicated) u64.
// ===========================================================================
#define GEMM64(WL4, XL, NCHUNK, KOFF)                                          \
    int tid = threadIdx.x, jj = tid >> 3, bp = tid & 7;                        \
    __shared__ u64  Ws[2][64][34];                                             \
    __shared__ float Xs[2][32][18];                                            \
    u64 accA = 0ull, accB = 0ull;                                              \
    const int r0 = tid >> 3, c0 = (tid * 4) & 31;                              \
    const int r1 = 32 + r0,  c1 = c0;                                          \
    const int xk = tid & 31, xb = tid >> 5;                                    \
    float4 w0, w1; float x0, x1;                                               \
    w0 = WL4(r0, (KOFF) + c0); w1 = WL4(r1, (KOFF) + c1);                      \
    x0 = XL(xb, (KOFF) + xk);  x1 = XL(xb + 8, (KOFF) + xk);                   \
    {                                                                          \
        ulonglong2* p0 = (ulonglong2*)&Ws[0][r0][c0];                          \
        p0[0] = make_ulonglong2(pack2(w0.x), pack2(w0.y));                     \
        p0[1] = make_ulonglong2(pack2(w0.z), pack2(w0.w));                     \
        ulonglong2* p1 = (ulonglong2*)&Ws[0][r1][c1];                          \
        p1[0] = make_ulonglong2(pack2(w1.x), pack2(w1.y));                     \
        p1[1] = make_ulonglong2(pack2(w1.z), pack2(w1.w));                     \
        Xs[0][xk][xb] = x0; Xs[0][xk][xb + 8] = x1;                            \
    }                                                                          \
    __syncthreads();                                                           \
    for (int ch = 0; ch < (NCHUNK); ch++) {                                    \
        int cur = ch & 1;                                                      \
        if (ch + 1 < (NCHUNK)) {                                               \
            int kb = (KOFF) + (ch + 1) * 32;                                   \
            w0 = WL4(r0, kb + c0); w1 = WL4(r1, kb + c1);                      \
            x0 = XL(xb, kb + xk);  x1 = XL(xb + 8, kb + xk);                   \
        }                                                                      \
        _Pragma("unroll")                                                      \
        for (int k = 0; k < 32; k++) {                                         \
            u64 xv = *(const u64*)&Xs[cur][k][bp * 2];                         \
            fma2(accA, Ws[cur][jj][k],      xv);                               \
            fma2(accB, Ws[cur][32 + jj][k], xv);                               \
        }                                                                      \
        if (ch + 1 < (NCHUNK)) {                                               \
            int nxt = cur ^ 1;                                                 \
            ulonglong2* p0 = (ulonglong2*)&Ws[nxt][r0][c0];                    \
            p0[0] = make_ulonglong2(pack2(w0.x), pack2(w0.y));                 \
            p0[1] = make_ulonglong2(pack2(w0.z), pack2(w0.w));                 \
            ulonglong2* p1 = (ulonglong2*)&Ws[nxt][r1][c1];                    \
            p1[0] = make_ulonglong2(pack2(w1.x), pack2(w1.y));                 \
            p1[1] = make_ulonglong2(pack2(w1.z), pack2(w1.w));                 \
            Xs[nxt][xk][xb] = x0; Xs[nxt][xk][xb + 8] = x1;                    \
        }                                                                      \
        __syncthreads();                                                       \
    }                                                                          \
    float2 vA = unpack2(accA), vB = unpack2(accB);

// ---------------------------------------------------------------------------
// K1: qproj partials.  grid (16 jb, 8 ks), 256 thr
__global__ __launch_bounds__(256) void k_qproj(const float* __restrict__ dec_h,
                                               const float* __restrict__ Wq) {
    int j0 = blockIdx.x * 64, ks = blockIdx.y;
#define WL4(r, k) (*(const float4*)&Wq[(size_t)(j0 + (r)) * D_ + (k)])
#define XLD(b, k) dec_h[(size_t)(b) * D_ + (k)]
    GEMM64(WL4, XLD, 4, ks * 128)
#undef WL4
#undef XLD
    float* o = g_qp + (size_t)ks * (B_ * D_);
    o[(size_t)(2 * bp)     * D_ + j0 + jj]      = vA.x;
    o[(size_t)(2 * bp + 1) * D_ + j0 + jj]      = vA.y;
    o[(size_t)(2 * bp)     * D_ + j0 + 32 + jj] = vB.x;
    o[(size_t)(2 * bp + 1) * D_ + j0 + 32 + jj] = vB.y;
}

// ---------------------------------------------------------------------------
// K2: qt[b][d][h] = SCALE * Wk_h^T q_h (sums the 8 qproj partials)
__global__ __launch_bounds__(256) void k_qtilde(const float* __restrict__ Wk) {
    int h = blockIdx.x >> 2, d0 = (blockIdx.x & 3) * 256, tid = threadIdx.x;
    __shared__ u64 qs2[64 * 8];          // [j][bpair]
    #pragma unroll
    for (int i = 0; i < 2; i++) {
        int idx = i * 256 + tid; int j = idx >> 3, bpp = idx & 7;
        float a = 0.f, bb = 0.f;
        #pragma unroll
        for (int ks = 0; ks < 8; ks++) {
            a  += g_qp[(size_t)ks * (B_ * D_) + (2 * bpp)     * D_ + h * HD_ + j];
            bb += g_qp[(size_t)ks * (B_ * D_) + (2 * bpp + 1) * D_ + h * HD_ + j];
        }
        qs2[j * 8 + bpp] = pack2b(a, bb);
    }
    __syncthreads();
    u64 acc[8];
    #pragma unroll
    for (int bp = 0; bp < 8; bp++) acc[bp] = 0ull;
    #pragma unroll 4
    for (int j = 0; j < HD_; j++) {
        u64 w2 = pack2(Wk[(size_t)(h * HD_ + j) * D_ + d0 + tid]);
        #pragma unroll
        for (int bp = 0; bp < 8; bp++) fma2(acc[bp], w2, qs2[j * 8 + bp]);
    }
    #pragma unroll
    for (int bp = 0; bp < 8; bp++) {
        float2 v = unpack2(acc[bp]);
        g_qt[(size_t)(2 * bp)     * D_ * NH_ + (d0 + tid) * NH_ + h] = 0.125f * v.x;
        g_qt[(size_t)(2 * bp + 1) * D_ * NH_ + (d0 + tid) * NH_ + h] = 0.125f * v.y;
    }
}

// ---------------------------------------------------------------------------
// K3 (pass A): scores[b][h][t].  grid (16, 16), 128 thr.
// Thread owns 2 t-rows (tid, tid+128) x all 16 heads (16 u64 accs).
// smem: enc chunk TRANSPOSED es[d][row] (pitch 258 -> conflict-free scalar
// reads); qt chunk pre-packed qs2[d][8] u64 read as 4 broadcast LDS.128.
// LDS:fma2 = 72:256 per chunk (vs 80:64 in v2).
__global__ __launch_bounds__(128) void k_scores(const float* __restrict__ enc) {
    const int b = blockIdx.x, t0 = blockIdx.y * 256, tid = threadIdx.x;
    __shared__ float es[2][16][258];
    __shared__ __align__(16) u64 qs2[2][16][8];
    const float* encb = enc + ((size_t)b * T_ + t0) * D_;
    const float* qtb  = g_qt + (size_t)b * D_ * NH_;

    const int lr = tid >> 2, lc = (tid & 3) * 4;    // loader: 8 float4 rows
    const int qd = tid >> 3, qp8 = tid & 7;         // q loader

    u64 accA[8], accB[8];
    #pragma unroll
    for (int hp = 0; hp < 8; hp++) { accA[hp] = 0ull; accB[hp] = 0ull; }

    float4 pe[8]; float2 pq;
    #pragma unroll
    for (int kk = 0; kk < 8; kk++)
        pe[kk] = *(const float4*)&encb[(size_t)(lr + 32 * kk) * D_ + lc];
    pq = *(const float2*)&qtb[(size_t)qd * NH_ + 2 * qp8];
    #pragma unroll
    for (int kk = 0; kk < 8; kk++) {
        int r = lr + 32 * kk;
        es[0][lc + 0][r] = pe[kk].x; es[0][lc + 1][r] = pe[kk].y;
        es[0][lc + 2][r] = pe[kk].z; es[0][lc + 3][r] = pe[kk].w;
    }
    qs2[0][qd][qp8] = pack2b(pq.x, pq.y);
    __syncthreads();

    for (int ch = 0; ch < 64; ch++) {
        int cur = ch & 1;
        if (ch + 1 < 64) {
            int dc = (ch + 1) * 16;
            #pragma unroll
            for (int kk = 0; kk < 8; kk++)
                pe[kk] = *(const float4*)&encb[(size_t)(lr + 32 * kk) * D_ + dc + lc];
            pq = *(const float2*)&qtb[(size_t)(dc + qd) * NH_ + 2 * qp8];
        }
        #pragma unroll
        for (int d = 0; d < 16; d++) {
            u64 e0 = pack2(es[cur][d][tid]);
            u64 e1 = pack2(es[cur][d][tid + 128]);
            const ulonglong2* qp = (const ulonglong2*)&qs2[cur][d][0];
            ulonglong2 qa = qp[0], qb = qp[1], qc = qp[2], qd2 = qp[3];
            fma2(accA[0], e0, qa.x); fma2(accB[0], e1, qa.x);
            fma2(accA[1], e0, qa.y); fma2(accB[1], e1, qa.y);
            fma2(accA[2], e0, qb.x); fma2(accB[2], e1, qb.x);
            fma2(accA[3], e0, qb.y); fma2(accB[3], e1, qb.y);
            fma2(accA[4], e0, qc.x); fma2(accB[4], e1, qc.x);
            fma2(accA[5], e0, qc.y); fma2(accB[5], e1, qc.y);
            fma2(accA[6], e0, qd2.x); fma2(accB[6], e1, qd2.x);
            fma2(accA[7], e0, qd2.y); fma2(accB[7], e1, qd2.y);
        }
        if (ch + 1 < 64) {
            int nxt = cur ^ 1;
            #pragma unroll
            for (int kk = 0; kk < 8; kk++) {
                int r = lr + 32 * kk;
                es[nxt][lc + 0][r] = pe[kk].x; es[nxt][lc + 1][r] = pe[kk].y;
                es[nxt][lc + 2][r] = pe[kk].z; es[nxt][lc + 3][r] = pe[kk].w;
            }
            qs2[nxt][qd][qp8] = pack2b(pq.x, pq.y);
        }
        __syncthreads();
    }
    int tA = t0 + tid, tB = t0 + 128 + tid;
    #pragma unroll
    for (int hp = 0; hp < 8; hp++) {
        float2 vA = unpack2(accA[hp]), vB = unpack2(accB[hp]);
        g_sc[((size_t)b * NH_ + 2 * hp    ) * T_ + tA] = vA.x;
        g_sc[((size_t)b * NH_ + 2 * hp + 1) * T_ + tA] = vA.y;
        g_sc[((size_t)b * NH_ + 2 * hp    ) * T_ + tB] = vB.x;
        g_sc[((size_t)b * NH_ + 2 * hp + 1) * T_ + tB] = vB.y;
    }
}

// ---------------------------------------------------------------------------
// K4: softmax over t per (b,h), [b][h][t], coalesced float4, fast exp
__global__ __launch_bounds__(256) void k_softmax() {
    int bh = blockIdx.x, tid = threadIdx.x;
    const float4* sc4 = (const float4*)(g_sc + (size_t)bh * T_);
    float4*       at4 = (float4*)      (g_at + (size_t)bh * T_);
    __shared__ float red[8];
    __shared__ float sbc;

    float4 v[4];
    float m = -1e30f;
    #pragma unroll
    for (int k = 0; k < 4; k++) {
        v[k] = sc4[(k << 8) + tid];
        m = fmaxf(m, fmaxf(fmaxf(v[k].x, v[k].y), fmaxf(v[k].z, v[k].w)));
    }
    #pragma unroll
    for (int o = 16; o > 0; o >>= 1) m = fmaxf(m, __shfl_xor_sync(0xffffffffu, m, o));
    if ((tid & 31) == 0) red[tid >> 5] = m;
    __syncthreads();
    if (tid == 0) {
        float mm = red[0];
        #pragma unroll
        for (int i = 1; i < 8; i++) mm = fmaxf(mm, red[i]);
        sbc = mm;
    }
    __syncthreads();
    m = sbc;
    float s = 0.f;
    #pragma unroll
    for (int k = 0; k < 4; k++) {
        v[k].x = __expf(v[k].x - m); v[k].y = __expf(v[k].y - m);
        v[k].z = __expf(v[k].z - m); v[k].w = __expf(v[k].w - m);
        s += (v[k].x + v[k].y) + (v[k].z + v[k].w);
    }
    s = wred(s);
    __syncthreads();
    if ((tid & 31) == 0) red[tid >> 5] = s;
    __syncthreads();
    if (tid == 0) {
        float ss = 0.f;
        #pragma unroll
        for (int i = 0; i < 8; i++) ss += red[i];
        sbc = 1.f / ss;
    }
    __syncthreads();
    float inv = sbc;
    #pragma unroll
    for (int k = 0; k < 4; k++) {
        v[k].x *= inv; v[k].y *= inv; v[k].z *= inv; v[k].w *= inv;
        at4[(k << 8) + tid] = v[k];
    }
}

// ---------------------------------------------------------------------------
// K5 (pass B): u_part[c][b][h][d], 128-row chunks   grid (16,32), 256 thr
__global__ __launch_bounds__(256) void k_wsum(const float* __restrict__ enc) {
    int b = blockIdx.x, c = blockIdx.y, tid = threadIdx.x;
    __shared__ float w_s[TCH_][18];
    #pragma unroll
    for (int i = 0; i < 8; i++) {
        int idx = (i << 8) + tid;
        int h = idx >> 7, t = idx & 127;
        w_s[t][h] = g_at[((size_t)b * NH_ + h) * T_ + c * TCH_ + t];
    }
    __syncthreads();

    u64 u[4][8];
    #pragma unroll
    for (int d = 0; d < 4; d++)
        #pragma unroll
        for (int hp = 0; hp < 8; hp++) u[d][hp] = 0ull;

    const float4* e4 = (const float4*)(enc + ((size_t)b * T_ + (size_t)c * TCH_) * D_) + tid;
    #pragma unroll 8
    for (int t = 0; t < TCH_; t++) {
        float4 ev = e4[(size_t)t * (D_ / 4)];
        const u64* wp = (const u64*)&w_s[t][0];
        u64 e0 = pack2(ev.x), e1 = pack2(ev.y), e2 = pack2(ev.z), e3 = pack2(ev.w);
        #pragma unroll
        for (int hp = 0; hp < 8; hp++) {
            u64 w2 = wp[hp];
            fma2(u[0][hp], e0, w2);
            fma2(u[1][hp], e1, w2);
            fma2(u[2][hp], e2, w2);
            fma2(u[3][hp], e3, w2);
        }
    }
    #pragma unroll
    for (int hp = 0; hp < 8; hp++) {
        float2 a0 = unpack2(u[0][hp]), a1 = unpack2(u[1][hp]),
               a2 = unpack2(u[2][hp]), a3 = unpack2(u[3][hp]);
        float4 lo = make_float4(a0.x, a1.x, a2.x, a3.x);
        float4 hi = make_float4(a0.y, a1.y, a2.y, a3.y);
        size_t base = (((size_t)c * B_ + b) * NH_) * D_ + 4 * tid;
        *(float4*)(g_up + base + (size_t)(2 * hp)     * D_) = lo;
        *(float4*)(g_up + base + (size_t)(2 * hp + 1) * D_) = hi;
    }
}

// ---------------------------------------------------------------------------
// K6: u = sum_c u_part
__global__ __launch_bounds__(256) void k_combine() {
    int idx = blockIdx.x * 256 + threadIdx.x;
    float s = 0.f;
    #pragma unroll
    for (int c = 0; c < NC_; c++) s += g_up[(size_t)c * (B_ * NH_ * D_) + idx];
    g_u[idx] = s;
}

// ---------------------------------------------------------------------------
// K7: ctx partials = Wv . u     grid (16 jb, 8 ks)
__global__ __launch_bounds__(256) void k_ctx(const float* __restrict__ Wv) {
    int j0 = blockIdx.x * 64, ks = blockIdx.y;
    int h  = blockIdx.x;
#define WL4(r, k) (*(const float4*)&Wv[(size_t)(j0 + (r)) * D_ + (k)])
#define XLD(b, k) g_u[((size_t)(b) * NH_ + h) * D_ + (k)]
    GEMM64(WL4, XLD, 4, ks * 128)
#undef WL4
#undef XLD
    float* o = g_cp + (size_t)ks * (B_ * D_);
    o[(size_t)(2 * bp)     * D_ + j0 + jj]      = vA.x;
    o[(size_t)(2 * bp + 1) * D_ + j0 + jj]      = vA.y;
    o[(size_t)(2 * bp)     * D_ + j0 + 32 + jj] = vB.x;
    o[(size_t)(2 * bp + 1) * D_ + j0 + 32 + jj] = vB.y;
}

// ---------------------------------------------------------------------------
// K8: ctx = sum of 8 ctx partials   grid 16, 256 thr, float4
__global__ __launch_bounds__(256) void k_ctxsum() {
    int i = (blockIdx.x * 256 + threadIdx.x) * 4;
    float4 s = *(const float4*)&g_cp[i];
    #pragma unroll
    for (int ks = 1; ks < 8; ks++) {
        float4 p = *(const float4*)&g_cp[(size_t)ks * (B_ * D_) + i];
        s.x += p.x; s.y += p.y; s.z += p.z; s.w += p.w;
    }
    *(float4*)&g_ctx[i] = s;
}

// ---------------------------------------------------------------------------
// K9: ffn1 partials = cat(dec_h, ctx) @ W1^T   grid (64 jb, 4 ks)
__global__ __launch_bounds__(256) void k_ffn1(const float* __restrict__ dec_h,
                                              const float* __restrict__ W1) {
    int j0 = blockIdx.x * 64, ks = blockIdx.y;
#define WL4(r, k) (*(const float4*)&W1[(size_t)(j0 + (r)) * (2 * D_) + (k)])
#define XLD(b, k) ((k) < D_ ? dec_h[(size_t)(b) * D_ + (k)]                    \
                            : g_ctx[(size_t)(b) * D_ + (k) - D_])
    GEMM64(WL4, XLD, 16, ks * 512)
#undef WL4
#undef XLD
    float* o = g_h4 + (size_t)ks * (B_ * 4 * D_);
    o[(size_t)(2 * bp)     * (4 * D_) + j0 + jj]      = vA.x;
    o[(size_t)(2 * bp + 1) * (4 * D_) + j0 + jj]      = vA.y;
    o[(size_t)(2 * bp)     * (4 * D_) + j0 + 32 + jj] = vB.x;
    o[(size_t)(2 * bp + 1) * (4 * D_) + j0 + 32 + jj] = vB.y;
}

// ---------------------------------------------------------------------------
// K10: hb = silu(sum of 4 ffn1 partials)   grid 64, 256 thr, float4
__global__ __launch_bounds__(256) void k_silu() {
    int i = (blockIdx.x * 256 + threadIdx.x) * 4;
    float4 s = *(const float4*)&g_h4[i];
    #pragma unroll
    for (int ks = 1; ks < 4; ks++) {
        float4 p = *(const float4*)&g_h4[(size_t)ks * (B_ * 4 * D_) + i];
        s.x += p.x; s.y += p.y; s.z += p.z; s.w += p.w;
    }
    float4 r;
    r.x = s.x / (1.f + __expf(-s.x));
    r.y = s.y / (1.f + __expf(-s.y));
    r.z = s.z / (1.f + __expf(-s.z));
    r.w = s.w / (1.f + __expf(-s.w));
    *(float4*)&g_hb[i] = r;
}

// ---------------------------------------------------------------------------
// K11: ffn2 partials = hb @ W2^T   grid (16 jb, 8 ks)
__global__ __launch_bounds__(256) void k_ffn2(const float* __restrict__ W2) {
    int j0 = blockIdx.x * 64, ks = blockIdx.y;
#define WL4(r, k) (*(const float4*)&W2[(size_t)(j0 + (r)) * (4 * D_) + (k)])
#define XLD(b, k) g_hb[(size_t)(b) * (4 * D_) + (k)]
    GEMM64(WL4, XLD, 16, ks * 512)
#undef WL4
#undef XLD
    float* o = g_o8 + (size_t)ks * (B_ * D_);
    o[(size_t)(2 * bp)     * D_ + j0 + jj]      = vA.x;
    o[(size_t)(2 * bp + 1) * D_ + j0 + jj]      = vA.y;
    o[(size_t)(2 * bp)     * D_ + j0 + 32 + jj] = vB.x;
    o[(size_t)(2 * bp + 1) * D_ + j0 + 32 + jj] = vB.y;
}

// ---------------------------------------------------------------------------
// K12: out = sum of 8 ffn2 partials   grid 16, 256 thr, float4
__global__ __launch_bounds__(256) void k_fin(float* __restrict__ outp) {
    int i = (blockIdx.x * 256 + threadIdx.x) * 4;
    float4 s = *(const float4*)&g_o8[i];
    #pragma unroll
    for (int ks = 1; ks < 8; ks++) {
        float4 p = *(const float4*)&g_o8[(size_t)ks * (B_ * D_) + i];
        s.x += p.x; s.y += p.y; s.z += p.z; s.w += p.w;
    }
    *(float4*)&outp[i] = s;
}

// ---------------------------------------------------------------------------
extern "C" void kernel_launch(void* const* d_in, const int* in_sizes, int n_in,
                              void* d_out, int out_size) {
    const float* dec_h = (const float*)d_in[0];
    const float* enc   = (const float*)d_in[1];
    const float* Wq    = (const float*)d_in[2];
    const float* Wk    = (const float*)d_in[3];
    const float* Wv    = (const float*)d_in[4];
    const float* W1    = (const float*)d_in[5];
    const float* W2    = (const float*)d_in[6];
    float* outp = (float*)d_out;

    k_qproj  <<<dim3(16, 8), 256>>>(dec_h, Wq);
    k_qtilde <<<64, 256>>>(Wk);
    k_scores <<<dim3(16, 16), 128>>>(enc);
    k_softmax<<<256, 256>>>();
    k_wsum   <<<dim3(16, 32), 256>>>(enc);
    k_combine<<<1024, 256>>>();
    k_ctx    <<<dim3(16, 8), 256>>>(Wv);
    k_ctxsum <<<16, 256>>>();
    k_ffn1   <<<dim3(64, 4), 256>>>(dec_h, W1);
    k_silu   <<<64, 256>>>();
    k_ffn2   <<<dim3(16, 8), 256>>>(W2);
    k_fin    <<<16, 256>>>(outp);
}